// round 8
// baseline (speedup 1.0000x reference)
#include <cuda_runtime.h>
#include <cstdint>

// B=16, C=4, H=1024, W=1024
// x: [B, C, H, W] fp32 ; out: [B, H, C, W] fp32
//
// Persistent double-buffered TMA pipeline.
// 912 CTAs (152 SM x 6), 256 threads. Each CTA loops over ~18 (b,h) tiles
// (tile = cta + i*912). Per iteration: issue cp.async.bulk for tile i+1 into
// the spare smem buffer, then wait on tile i's mbarrier, compute moments ->
// scores -> softmax -> effective 4x4 transform, and stream out the result.
// Steady state: next tile's 16KB load fully overlaps current tile's work.

#define H_DIM 1024
#define W_DIM 1024
#define THREADS 256
#define NCTA 912              // 152 SMs * 6 CTAs
#define NTILES (16 * H_DIM)   // 16384

__device__ __forceinline__ uint32_t smem_u32(const void* p) {
    return (uint32_t)__cvta_generic_to_shared(p);
}

__device__ __forceinline__ void mbar_wait(uint32_t mbar_a, uint32_t parity) {
    asm volatile(
        "{\n\t"
        ".reg .pred P;\n\t"
        "WAIT_%=:\n\t"
        "mbarrier.try_wait.parity.acquire.cta.shared::cta.b64 P, [%0], %1;\n\t"
        "@P bra DONE_%=;\n\t"
        "bra WAIT_%=;\n\t"
        "DONE_%=:\n\t"
        "}"
        :: "r"(mbar_a), "r"(parity) : "memory");
}

__global__ __launch_bounds__(THREADS, 6)
void fused_attn_kernel(const float* __restrict__ x,
                       const float* __restrict__ wq, const float* __restrict__ bq,
                       const float* __restrict__ wk, const float* __restrict__ bk,
                       const float* __restrict__ wv, const float* __restrict__ bv,
                       float* __restrict__ out)
{
    const int cta  = blockIdx.x;
    const int tid  = threadIdx.x;
    const int lane = tid & 31;
    const int warp = tid >> 5;
    const int w0   = tid << 2;

    __shared__ alignas(128) float xt[2][4][W_DIM];   // 2 x 16KB tile buffers
    __shared__ alignas(8) uint64_t mbar[2];
    __shared__ float s_red[8][16];
    __shared__ float s_gm[16];
    __shared__ float s_sc[16];
    __shared__ float s_attn[16];
    __shared__ float s_fin[20];                      // A_eff[16] | b_eff[4]

    const uint32_t mbar_a0 = smem_u32(&mbar[0]);
    const uint32_t mbar_a1 = smem_u32(&mbar[1]);

    if (tid == 0) {
        asm volatile("mbarrier.init.shared.b64 [%0], 1;" :: "r"(mbar_a0) : "memory");
        asm volatile("mbarrier.init.shared.b64 [%0], 1;" :: "r"(mbar_a1) : "memory");
        asm volatile("fence.mbarrier_init.release.cluster;" ::: "memory");
    }
    __syncthreads();

    const int ntiles = (NTILES - cta + NCTA - 1) / NCTA;   // tiles for this CTA
    if (ntiles <= 0) return;

    // ---- Issue load of tile 0 into buffer 0
    if (tid == 0) {
        const int bh0 = cta;
        const int b = bh0 >> 10, h = bh0 & (H_DIM - 1);
        const float* src = x + ((size_t)(b << 2) * H_DIM + h) * W_DIM;
        asm volatile("mbarrier.arrive.expect_tx.shared.b64 _, [%0], %1;"
                     :: "r"(mbar_a0), "r"(16384u) : "memory");
        #pragma unroll
        for (int c = 0; c < 4; c++) {
            asm volatile(
                "cp.async.bulk.shared::cluster.global.mbarrier::complete_tx::bytes "
                "[%0], [%1], %2, [%3];"
                :: "r"(smem_u32(&xt[0][c][0])),
                   "l"(src + (size_t)c * (H_DIM * W_DIM)),
                   "r"(4096u), "r"(mbar_a0) : "memory");
        }
    }

    for (int it = 0; it < ntiles; it++) {
        const int cur = it & 1;
        const int bh  = cta + it * NCTA;
        const uint32_t mcur = cur ? mbar_a1 : mbar_a0;

        // ---- Issue next tile's load into the spare buffer (free since it-1's
        //      compute finished before the trailing __syncthreads of it-1).
        if (tid == 0 && it + 1 < ntiles) {
            const int nxt  = cur ^ 1;
            const int bhn  = cta + (it + 1) * NCTA;
            const int bn = bhn >> 10, hn = bhn & (H_DIM - 1);
            const float* src = x + ((size_t)(bn << 2) * H_DIM + hn) * W_DIM;
            const uint32_t mnxt = nxt ? mbar_a1 : mbar_a0;
            asm volatile("mbarrier.arrive.expect_tx.shared.b64 _, [%0], %1;"
                         :: "r"(mnxt), "r"(16384u) : "memory");
            #pragma unroll
            for (int c = 0; c < 4; c++) {
                asm volatile(
                    "cp.async.bulk.shared::cluster.global.mbarrier::complete_tx::bytes "
                    "[%0], [%1], %2, [%3];"
                    :: "r"(smem_u32(&xt[nxt][c][0])),
                       "l"(src + (size_t)c * (H_DIM * W_DIM)),
                       "r"(4096u), "r"(mnxt) : "memory");
            }
        }

        // ---- Wait for current tile (parity = use-count of this buffer mod 2)
        mbar_wait(mcur, (uint32_t)((it >> 1) & 1));

        // ---- Phase 1: moments
        float4 xc[4];
        #pragma unroll
        for (int c = 0; c < 4; c++)
            xc[c] = *reinterpret_cast<const float4*>(&xt[cur][c][w0]);

        float r[16];
        #pragma unroll
        for (int i = 0; i < 16; i++) r[i] = 0.f;

        #pragma unroll
        for (int p = 0; p < 4; p++) {
            const float x0 = (&xc[0].x)[p];
            const float x1 = (&xc[1].x)[p];
            const float x2 = (&xc[2].x)[p];
            const float x3 = (&xc[3].x)[p];
            r[0] = fmaf(x0, x0, r[0]);
            r[1] = fmaf(x0, x1, r[1]);
            r[2] = fmaf(x0, x2, r[2]);
            r[3] = fmaf(x0, x3, r[3]);
            r[4] = fmaf(x1, x1, r[4]);
            r[5] = fmaf(x1, x2, r[5]);
            r[6] = fmaf(x1, x3, r[6]);
            r[7] = fmaf(x2, x2, r[7]);
            r[8] = fmaf(x2, x3, r[8]);
            r[9] = fmaf(x3, x3, r[9]);
            r[10] += x0; r[11] += x1; r[12] += x2; r[13] += x3;
        }

        // ---- Interleaved butterfly: 16 values in 16 SHFL
        #pragma unroll
        for (int i = 0; i < 8; i++) {
            const float a = r[i], bb = r[i + 8];
            const float send = (lane & 16) ? a : bb;
            const float recv = __shfl_xor_sync(0xFFFFFFFFu, send, 16);
            r[i] = ((lane & 16) ? bb : a) + recv;
        }
        #pragma unroll
        for (int i = 0; i < 4; i++) {
            const float a = r[i], bb = r[i + 4];
            const float send = (lane & 8) ? a : bb;
            const float recv = __shfl_xor_sync(0xFFFFFFFFu, send, 8);
            r[i] = ((lane & 8) ? bb : a) + recv;
        }
        #pragma unroll
        for (int i = 0; i < 2; i++) {
            const float a = r[i], bb = r[i + 2];
            const float send = (lane & 4) ? a : bb;
            const float recv = __shfl_xor_sync(0xFFFFFFFFu, send, 4);
            r[i] = ((lane & 4) ? bb : a) + recv;
        }
        {
            const float a = r[0], bb = r[1];
            const float send = (lane & 2) ? a : bb;
            const float recv = __shfl_xor_sync(0xFFFFFFFFu, send, 2);
            r[0] = ((lane & 2) ? bb : a) + recv;
        }
        r[0] += __shfl_xor_sync(0xFFFFFFFFu, r[0], 1);
        if (!(lane & 1)) s_red[warp][(lane >> 1) & 15] = r[0];
        __syncthreads();

        // ---- Epilogue: warp 0
        if (warp == 0) {
            if (lane < 16) {
                float s = 0.f;
                #pragma unroll
                for (int wdx = 0; wdx < 8; wdx++) s += s_red[wdx][lane];
                s_gm[lane] = s;
            }
            __syncwarp();

            if (lane < 16) {
                const int c = lane >> 2, d = lane & 3;
                const float m0 = s_gm[10], m1 = s_gm[11], m2 = s_gm[12], m3 = s_gm[13];
                float wqc[4], wkd[4];
                #pragma unroll
                for (int i = 0; i < 4; i++) { wqc[i] = wq[c * 4 + i]; wkd[i] = wk[d * 4 + i]; }
                const float bqc = bq[c], bkd = bk[d];

                float s = 0.f;
                #pragma unroll
                for (int i = 0; i < 4; i++) {
                    float acc = 0.f;
                    #pragma unroll
                    for (int j = 0; j < 4; j++) {
                        const int lo = i < j ? i : j, hi = i < j ? j : i;
                        const int gi = lo * 4 - (lo * (lo - 1)) / 2 + (hi - lo);
                        acc = fmaf(s_gm[gi], wkd[j], acc);
                    }
                    s = fmaf(wqc[i], acc, s);
                }
                const float tq = wqc[0]*m0 + wqc[1]*m1 + wqc[2]*m2 + wqc[3]*m3;
                const float tk = wkd[0]*m0 + wkd[1]*m1 + wkd[2]*m2 + wkd[3]*m3;
                s += bqc * tk + bkd * tq + (float)W_DIM * bqc * bkd;
                s_sc[lane] = s * 0.03125f;       // 1/sqrt(1024)
            }
            __syncwarp();

            if (lane < 4) {
                const int c = lane;
                float m = s_sc[c * 4];
                #pragma unroll
                for (int d = 1; d < 4; d++) m = fmaxf(m, s_sc[c * 4 + d]);
                float e[4], sum = 0.f;
                #pragma unroll
                for (int d = 0; d < 4; d++) { e[d] = __expf(s_sc[c * 4 + d] - m); sum += e[d]; }
                const float inv = __fdividef(1.0f, sum);
                #pragma unroll
                for (int d = 0; d < 4; d++) s_attn[c * 4 + d] = e[d] * inv;
            }
            __syncwarp();

            if (lane < 16) {
                const int c = lane >> 2, i = lane & 3;
                float s = 0.f;
                #pragma unroll
                for (int d = 0; d < 4; d++) s = fmaf(s_attn[c * 4 + d], wv[d * 4 + i], s);
                s_fin[lane] = s;
            }
            if (lane < 4) {
                float s = 0.f;
                #pragma unroll
                for (int d = 0; d < 4; d++) s = fmaf(s_attn[lane * 4 + d], bv[d], s);
                s_fin[16 + lane] = s;
            }
        }
        __syncthreads();

        // ---- Phase 2: out[c][w] = A_eff[c]·x[:,w] + b_eff[c]
        float ae[4][4], be[4];
        #pragma unroll
        for (int c = 0; c < 4; c++) {
            be[c] = s_fin[16 + c];
            #pragma unroll
            for (int i = 0; i < 4; i++) ae[c][i] = s_fin[c * 4 + i];
        }

        const int obase = (bh << 12) + w0;
        #pragma unroll
        for (int c = 0; c < 4; c++) {
            float4 rr;
            float* rp = &rr.x;
            #pragma unroll
            for (int j = 0; j < 4; j++) {
                float s = be[c];
                #pragma unroll
                for (int i = 0; i < 4; i++)
                    s = fmaf(ae[c][i], (&xc[i].x)[j], s);
                rp[j] = s;
            }
            __stcs(reinterpret_cast<float4*>(out + obase + (c << 10)), rr);
        }

        // Buffer `cur` fully consumed (xc in regs, stores issued); next reuse of
        // this buffer (iteration it+2) is gated by this barrier.
        __syncthreads();
    }
}

extern "C" void kernel_launch(void* const* d_in, const int* in_sizes, int n_in,
                              void* d_out, int out_size)
{
    const float* x  = (const float*)d_in[0];
    const float* wq = (const float*)d_in[1];
    const float* bq = (const float*)d_in[2];
    const float* wk = (const float*)d_in[3];
    const float* bk = (const float*)d_in[4];
    const float* wv = (const float*)d_in[5];
    const float* bv = (const float*)d_in[6];
    float* out = (float*)d_out;

    dim3 grid(NCTA);
    dim3 block(THREADS);
    fused_attn_kernel<<<grid, block>>>(x, wq, bq, wk, bk, wv, bv, out);
}

// round 9
// speedup vs baseline: 1.0999x; 1.0999x over previous
#include <cuda_runtime.h>

// B=16, C=4, H=1024, W=1024
// x: [B, C, H, W] fp32 ; out: [B, H, C, W] fp32
//
// Moment-based fused kernel, single-barrier / warp-redundant epilogue.
// One CTA per (b,h), 256 threads x 4 w (register-resident x).
//   Phase 1: per-thread moments G (10 sym) + m (4), butterfly reduce (16 SHFL),
//            per-warp partials -> smem, ONE __syncthreads.
//   Epilogue: EVERY warp independently: 8-warp sum, broadcast 14 moments via
//            SHFL, scores in lanes 0-15, softmax via shfl_xor in 4-groups,
//            A_eff = attn@Wv / b_eff = attn@bv, 20-value broadcast. No 2nd
//            barrier, no warp-0 serialization -> stores start earlier.
//   Phase 2: out = A_eff x + b_eff, streaming float4 stores.

#define H_DIM 1024
#define W_DIM 1024
#define THREADS 256

__global__ __launch_bounds__(THREADS, 5)
void fused_attn_kernel(const float* __restrict__ x,
                       const float* __restrict__ wq, const float* __restrict__ bq,
                       const float* __restrict__ wk, const float* __restrict__ bk,
                       const float* __restrict__ wv, const float* __restrict__ bv,
                       float* __restrict__ out)
{
    const int bh   = blockIdx.x;
    const int tid  = threadIdx.x;
    const int lane = tid & 31;
    const int warp = tid >> 5;
    const int w0   = tid << 2;

    __shared__ float s_red[8][16];     // per-warp reduced {G[10], m[4], 0, 0}

    // ---- Load x: 4 channels x float4, streaming
    const int b = bh >> 10;
    const int h = bh & (H_DIM - 1);
    const int base = ((b << 2) * H_DIM + h) * W_DIM + w0;

    float xv[4][4];
    #pragma unroll
    for (int c = 0; c < 4; c++) {
        const float4 t = __ldcs(reinterpret_cast<const float4*>(
                              x + base + c * (H_DIM * W_DIM)));
        xv[c][0] = t.x; xv[c][1] = t.y; xv[c][2] = t.z; xv[c][3] = t.w;
    }

    // ---- Phase 1 moments: r = {G00,G01,G02,G03,G11,G12,G13,G22,G23,G33, m0..m3, 0,0}
    float r[16];
    #pragma unroll
    for (int i = 0; i < 16; i++) r[i] = 0.f;

    #pragma unroll
    for (int p = 0; p < 4; p++) {
        const float x0 = xv[0][p], x1 = xv[1][p], x2 = xv[2][p], x3 = xv[3][p];
        r[0] = fmaf(x0, x0, r[0]);
        r[1] = fmaf(x0, x1, r[1]);
        r[2] = fmaf(x0, x2, r[2]);
        r[3] = fmaf(x0, x3, r[3]);
        r[4] = fmaf(x1, x1, r[4]);
        r[5] = fmaf(x1, x2, r[5]);
        r[6] = fmaf(x1, x3, r[6]);
        r[7] = fmaf(x2, x2, r[7]);
        r[8] = fmaf(x2, x3, r[8]);
        r[9] = fmaf(x3, x3, r[9]);
        r[10] += x0; r[11] += x1; r[12] += x2; r[13] += x3;
    }

    // ---- Interleaved butterfly: 16 values over 32 lanes in 16 SHFL
    #pragma unroll
    for (int i = 0; i < 8; i++) {
        const float a = r[i], bb = r[i + 8];
        const float send = (lane & 16) ? a : bb;
        const float recv = __shfl_xor_sync(0xFFFFFFFFu, send, 16);
        r[i] = ((lane & 16) ? bb : a) + recv;
    }
    #pragma unroll
    for (int i = 0; i < 4; i++) {
        const float a = r[i], bb = r[i + 4];
        const float send = (lane & 8) ? a : bb;
        const float recv = __shfl_xor_sync(0xFFFFFFFFu, send, 8);
        r[i] = ((lane & 8) ? bb : a) + recv;
    }
    #pragma unroll
    for (int i = 0; i < 2; i++) {
        const float a = r[i], bb = r[i + 2];
        const float send = (lane & 4) ? a : bb;
        const float recv = __shfl_xor_sync(0xFFFFFFFFu, send, 4);
        r[i] = ((lane & 4) ? bb : a) + recv;
    }
    {
        const float a = r[0], bb = r[1];
        const float send = (lane & 2) ? a : bb;
        const float recv = __shfl_xor_sync(0xFFFFFFFFu, send, 2);
        r[0] = ((lane & 2) ? bb : a) + recv;
    }
    r[0] += __shfl_xor_sync(0xFFFFFFFFu, r[0], 1);
    if (!(lane & 1)) s_red[warp][(lane >> 1) & 15] = r[0];

    __syncthreads();     // the ONLY block barrier

    // ---- Warp-redundant epilogue (every warp computes the full 4x4 transform)
    // 1) cross-warp sum: lane j (j<16) holds gm[j]
    float gmv = 0.f;
    if (lane < 16) {
        #pragma unroll
        for (int wdx = 0; wdx < 8; wdx++) gmv += s_red[wdx][lane];
    }
    // 2) broadcast 14 moments to all lanes
    float g[14];
    #pragma unroll
    for (int j = 0; j < 14; j++) g[j] = __shfl_sync(0xFFFFFFFFu, gmv, j);

    // 3) scores in lanes 0-15 (lane = c*4+d)
    float attn = 0.f;     // will hold softmax weight for this lane's (c,d)
    {
        const int c = (lane >> 2) & 3, d = lane & 3;
        float wqc[4], wkd[4];
        #pragma unroll
        for (int i = 0; i < 4; i++) {
            wqc[i] = __ldg(wq + c * 4 + i);
            wkd[i] = __ldg(wk + d * 4 + i);
        }
        const float bqc = __ldg(bq + c), bkd = __ldg(bk + d);

        float s = 0.f;
        #pragma unroll
        for (int i = 0; i < 4; i++) {
            float acc = 0.f;
            #pragma unroll
            for (int j = 0; j < 4; j++) {
                const int lo = i < j ? i : j, hi = i < j ? j : i;
                const int gi = lo * 4 - (lo * (lo - 1)) / 2 + (hi - lo);
                acc = fmaf(g[gi], wkd[j], acc);
            }
            s = fmaf(wqc[i], acc, s);
        }
        const float tq = wqc[0]*g[10] + wqc[1]*g[11] + wqc[2]*g[12] + wqc[3]*g[13];
        const float tk = wkd[0]*g[10] + wkd[1]*g[11] + wkd[2]*g[12] + wkd[3]*g[13];
        s += bqc * tk + bkd * tq + (float)W_DIM * bqc * bkd;
        s *= 0.03125f;    // 1/sqrt(1024)

        // 4) softmax across d within each 4-lane group (xor 1,2 stay in-group)
        float m = s;
        m = fmaxf(m, __shfl_xor_sync(0xFFFFFFFFu, m, 1));
        m = fmaxf(m, __shfl_xor_sync(0xFFFFFFFFu, m, 2));
        float e = __expf(s - m);
        float sum = e;
        sum += __shfl_xor_sync(0xFFFFFFFFu, sum, 1);
        sum += __shfl_xor_sync(0xFFFFFFFFu, sum, 2);
        attn = e * __fdividef(1.0f, sum);
    }

    // 5) A_eff/b_eff in lanes 0-15 (lane = c*4+i)
    float ae_mine = 0.f, be_mine = 0.f;
    {
        const int i = lane & 3;
        const int grp = lane & ~3;            // c*4
        #pragma unroll
        for (int d = 0; d < 4; d++) {
            const float ad = __shfl_sync(0xFFFFFFFFu, attn, grp + d);
            ae_mine = fmaf(ad, __ldg(wv + d * 4 + i), ae_mine);
            be_mine = fmaf(ad, __ldg(bv + d), be_mine);
        }
    }

    // 6) broadcast final transform to all lanes
    float ae[4][4], be[4];
    #pragma unroll
    for (int idx = 0; idx < 16; idx++)
        ae[idx >> 2][idx & 3] = __shfl_sync(0xFFFFFFFFu, ae_mine, idx);
    #pragma unroll
    for (int c = 0; c < 4; c++)
        be[c] = __shfl_sync(0xFFFFFFFFu, be_mine, c << 2);

    // ---- Phase 2: out[c][w] = A_eff[c]·x[:,w] + b_eff[c]
    const int obase = (bh << 12) + w0;
    #pragma unroll
    for (int c = 0; c < 4; c++) {
        float4 rr;
        float* rp = &rr.x;
        #pragma unroll
        for (int j = 0; j < 4; j++) {
            float s = be[c];
            #pragma unroll
            for (int i = 0; i < 4; i++) s = fmaf(ae[c][i], xv[i][j], s);
            rp[j] = s;
        }
        __stcs(reinterpret_cast<float4*>(out + obase + (c << 10)), rr);
    }
}

extern "C" void kernel_launch(void* const* d_in, const int* in_sizes, int n_in,
                              void* d_out, int out_size)
{
    const float* x  = (const float*)d_in[0];
    const float* wq = (const float*)d_in[1];
    const float* bq = (const float*)d_in[2];
    const float* wk = (const float*)d_in[3];
    const float* bk = (const float*)d_in[4];
    const float* wv = (const float*)d_in[5];
    const float* bv = (const float*)d_in[6];
    float* out = (float*)d_out;

    dim3 grid(16 * H_DIM);     // one CTA per (b,h)
    dim3 block(THREADS);
    fused_attn_kernel<<<grid, block>>>(x, wq, bq, wk, bk, wv, bv, out);
}